// round 6
// baseline (speedup 1.0000x reference)
#include <cuda_runtime.h>
#include <cuda_bf16.h>
#include <math.h>
#include <stdint.h>

#define B_  16
#define C_  128
#define O_  256
#define H_  96
#define W_  96
#define KH  5
#define HO  92
#define WO  92
#define HW_IN  (H_*W_)        // 9216
#define HW_OUT (HO*WO)        // 8464
#define KK  25
#define NPT 67                // ceil(8464/128)
#define NSTAGE 50             // 25 taps * 2 k64-chunks

// ---------------- device scratch (no allocation allowed) ----------------
// Channel-last bf16 planes: [path][b][pix(9216)][c(128)]
__device__ __align__(128) __nv_bfloat16 g_Ah[(size_t)2*B_*HW_IN*128];
__device__ __align__(128) __nv_bfloat16 g_Al[(size_t)B_*HW_IN*128];    // mu lo only
// Weights: [path][og][tap][split][o_local(128)][c(128)] ; path1 uses split 0 only
__device__ __align__(128) __nv_bfloat16 g_Wp[(size_t)2*2*KK*2*16384];
__device__ float g_Tp[2*B_*HW_IN];   // [path][b][pix]: path0 = sum mu^2, path1 = sum sigma
__device__ float g_S [B_*HW_OUT];
__device__ float g_sp[O_];

// ---------------- PTX helpers ----------------
__device__ __forceinline__ uint32_t smem_u32(const void* p){
    return (uint32_t)__cvta_generic_to_shared((void*)p);
}
__device__ __forceinline__ void cp16(uint32_t dst, const void* src){
    asm volatile("cp.async.cg.shared.global [%0], [%1], 16;\n" :: "r"(dst), "l"(src));
}
__device__ __forceinline__ void cp_commit(){ asm volatile("cp.async.commit_group;\n" ::: "memory"); }
template<int N> __device__ __forceinline__ void cp_wait(){
    asm volatile("cp.async.wait_group %0;\n" :: "n"(N) : "memory");
}
__device__ __forceinline__ void ldsm4(uint32_t* r, uint32_t addr){
    asm volatile("ldmatrix.sync.aligned.m8n8.x4.shared.b16 {%0,%1,%2,%3}, [%4];"
        : "=r"(r[0]), "=r"(r[1]), "=r"(r[2]), "=r"(r[3]) : "r"(addr));
}
#define MMA(acc, a, b0, b1)                                                        \
    asm volatile("mma.sync.aligned.m16n8k16.row.col.f32.bf16.bf16.f32 "            \
                 "{%0,%1,%2,%3},{%4,%5,%6,%7},{%8,%9},{%0,%1,%2,%3};"              \
                 : "+f"((acc)[0]), "+f"((acc)[1]), "+f"((acc)[2]), "+f"((acc)[3])  \
                 : "r"((a)[0]), "r"((a)[1]), "r"((a)[2]), "r"((a)[3]),             \
                   "r"(b0), "r"(b1))

// ---------------- prep kernels ----------------
__global__ void transpose_split_kernel(const float* __restrict__ mu,
                                       const float* __restrict__ sg) {
    __shared__ float ts[C_][65];
    int pt = blockIdx.x, b = blockIdx.y, path = blockIdx.z;
    const float* src = (path ? sg : mu) + (size_t)b * C_ * HW_IN + pt * 64;
    int tid = threadIdx.x;
    for (int i = tid; i < C_ * 64; i += 256) {
        int c = i >> 6, pi = i & 63;
        ts[c][pi] = src[(size_t)c * HW_IN + pi];
    }
    __syncthreads();
    size_t obase = (size_t)(path * B_ + b) * HW_IN * 128;
    int p0 = pt * 64;
    for (int i = tid; i < 64 * C_; i += 256) {
        int pi = i >> 7, c = i & 127;
        float v = ts[c][pi];
        __nv_bfloat16 hi = __float2bfloat16(v);
        size_t idx = obase + (size_t)(p0 + pi) * 128 + c;
        g_Ah[idx] = hi;
        if (path == 0)
            g_Al[(size_t)b * HW_IN * 128 + (size_t)(p0 + pi) * 128 + c] =
                __float2bfloat16(v - __bfloat162float(hi));
    }
    // fused channel sum: path0 -> sum mu^2, path1 -> sum sigma
    if (tid < 64) {
        float acc = 0.0f;
        #pragma unroll 8
        for (int c = 0; c < C_; ++c) {
            float v = ts[c][tid];
            acc += path ? v : v * v;
        }
        g_Tp[(size_t)(path * B_ + b) * HW_IN + p0 + tid] = acc;
    }
}

__global__ void wprep_kernel(const float* __restrict__ W,
                             const float* __restrict__ w_sigma) {
    int gid = blockIdx.x * blockDim.x + threadIdx.x;
    if (gid < O_) {
        float w = fmaxf(w_sigma[gid], -88.0f);
        g_sp[gid] = log1pf(expf(w));
    }
    if (gid >= O_ * C_) return;
    int o = gid >> 7, c = gid & 127;
    int og = o >> 7, ol = o & 127;
    const float* wp = W + ((size_t)o * C_ + c) * KK;
    int dst_in = ol * 128 + c;
    #pragma unroll
    for (int tap = 0; tap < KK; ++tap) {
        float w  = wp[tap];
        float w2 = w * w;
        __nv_bfloat16 h0 = __float2bfloat16(w);
        __nv_bfloat16 l0 = __float2bfloat16(w  - __bfloat162float(h0));
        size_t blk0 = (size_t)(((0 * 2 + og) * KK + tap) * 2);
        size_t blk1 = (size_t)(((1 * 2 + og) * KK + tap) * 2);
        g_Wp[(blk0 + 0) * 16384 + dst_in] = h0;
        g_Wp[(blk0 + 1) * 16384 + dst_in] = l0;
        g_Wp[(blk1 + 0) * 16384 + dst_in] = __float2bfloat16(w2);
    }
}

__global__ void boxsum_kernel() {
    int i = blockIdx.x * blockDim.x + threadIdx.x;
    if (i >= B_*HW_OUT) return;
    int b = i / HW_OUT;
    int p = i - b * HW_OUT;
    int y = p / WO;
    int x = p - y * WO;
    const float* t0 = g_Tp + (size_t)b * HW_IN;
    const float* t1 = g_Tp + (size_t)(B_ + b) * HW_IN;
    float acc = 0.0f;
    #pragma unroll
    for (int dy = 0; dy < KH; ++dy)
        #pragma unroll
        for (int dx = 0; dx < KH; ++dx) {
            int off = (y + dy) * W_ + (x + dx);
            acc += t0[off] + t1[off];
        }
    g_S[i] = acc;
}

// ---------------- main mma.sync conv (templated on path) ----------------
// PATH 0 (mu, 3-term): buffer = Ah|Al|Bh|Bl = 64KB, x2 = 128KB, 1 CTA/SM
// PATH 1 (sigma, 1-term): buffer = Ah|Bh = 32KB, x2 = 64KB, 2 CTA/SM
template<int PATH>
__global__ void __launch_bounds__(256, (PATH == 0 ? 1 : 2))
mma_conv_kernel(const float* __restrict__ bias, float* __restrict__ out) {
    constexpr uint32_t kBuf   = (PATH == 0) ? 65536u : 32768u;
    constexpr uint32_t kOffAL = 16384u;
    constexpr uint32_t kOffBH = (PATH == 0) ? 32768u : 16384u;
    constexpr uint32_t kOffBL = 49152u;
    constexpr int      kEP    = (PATH == 0) ? 132 : 128;

    extern __shared__ char smem[];
    uint32_t sb = smem_u32(smem);
    int tid = threadIdx.x;
    int lane = tid & 31, wid = tid >> 5;
    int warp_m = wid >> 2, warp_n = wid & 3;

    int ptile = blockIdx.x, b = blockIdx.y, og = blockIdx.z;

    // ---- staging setup ----
    int m_pix = tid & 127;
    int p  = ptile * 128 + m_pix;
    int pc = min(p, HW_OUT - 1);
    int py = pc / WO, px = pc - py * WO;
    const __nv_bfloat16* aplane =
        (tid < 128 ? g_Ah + (size_t)(PATH * B_ + b) * HW_IN * 128
                   : g_Al + (size_t)b * HW_IN * 128);
    uint32_t a_sm_off = (tid < 128 ? 0u : kOffAL) + (uint32_t)m_pix * 128;

    int bn = tid >> 1, bhalf = tid & 1;
    const char* wbase = (const char*)g_Wp +
        (size_t)((PATH * 2 + og) * KK) * 2 * 32768 + (size_t)bn * 256 + bhalf * 64;
    uint32_t b_sm_base = (uint32_t)bn * 128;

    auto stage = [&](int s, int buf) {
        int tap = s >> 1, kc = s & 1;
        int ki = tap / 5, kj = tap - ki * 5;
        if (PATH == 0 || tid < 128) {
            const char* arow =
                (const char*)(aplane + ((size_t)((py + ki) * W_ + (px + kj))) * 128)
                + kc * 128;
            uint32_t adst = sb + buf * kBuf + a_sm_off;
            int msw = m_pix & 7;
            #pragma unroll
            for (int j = 0; j < 8; ++j)
                cp16(adst + (uint32_t)((j ^ msw) << 4), arow + j * 16);
        }
        const char* bsrc = wbase + (size_t)tap * 2 * 32768 + kc * 128;
        uint32_t bdst = sb + buf * kBuf + b_sm_base;
        int nsw = bn & 7;
        #pragma unroll
        for (int j = 0; j < 4; ++j) {
            uint32_t so = (uint32_t)(((bhalf * 4 + j) ^ nsw) << 4);
            cp16(bdst + kOffBH + so, bsrc + j * 16);
            if (PATH == 0)
                cp16(bdst + kOffBL + so, bsrc + 32768 + j * 16);
        }
        cp_commit();
    };

    uint32_t rowbaseA = (uint32_t)(warp_m * 64 + (lane & 15)) * 128;
    uint32_t rowbaseB = (uint32_t)(warp_n * 32 + ((lane >> 4) << 3) + (lane & 7)) * 128;
    int lsw = lane & 7;
    uint32_t offA[4], offB[4];
    #pragma unroll
    for (int s = 0; s < 4; ++s) {
        offA[s] = (uint32_t)(((2 * s + (lane >> 4)) ^ lsw) << 4);
        offB[s] = (uint32_t)(((2 * s + ((lane >> 3) & 1)) ^ lsw) << 4);
    }

    float acc[4][4][4];
    #pragma unroll
    for (int mi = 0; mi < 4; ++mi)
        #pragma unroll
        for (int ni = 0; ni < 4; ++ni)
            #pragma unroll
            for (int j = 0; j < 4; ++j) acc[mi][ni][j] = 0.0f;

    stage(0, 0);

    for (int s = 0; s < NSTAGE; ++s) {
        int buf = s & 1;
        if (s + 1 < NSTAGE) { stage(s + 1, buf ^ 1); cp_wait<1>(); }
        else                { cp_wait<0>(); }
        __syncthreads();

        uint32_t base = sb + buf * kBuf;
        uint32_t aAh = base + rowbaseA;
        uint32_t aAl = base + kOffAL + rowbaseA;
        uint32_t aBh = base + kOffBH + rowbaseB;
        uint32_t aBl = base + kOffBL + rowbaseB;

        #pragma unroll
        for (int ks = 0; ks < 4; ++ks) {
            uint32_t ah[4][4], bh[2][4];
            #pragma unroll
            for (int mi = 0; mi < 4; ++mi)
                ldsm4(ah[mi], aAh + mi * 2048 + offA[ks]);
            #pragma unroll
            for (int n2 = 0; n2 < 2; ++n2)
                ldsm4(bh[n2], aBh + n2 * 2048 + offB[ks]);

            if (PATH == 0) {
                uint32_t al[4][4], bl[2][4];
                #pragma unroll
                for (int mi = 0; mi < 4; ++mi)
                    ldsm4(al[mi], aAl + mi * 2048 + offA[ks]);
                #pragma unroll
                for (int n2 = 0; n2 < 2; ++n2)
                    ldsm4(bl[n2], aBl + n2 * 2048 + offB[ks]);
                #pragma unroll
                for (int mi = 0; mi < 4; ++mi)
                    #pragma unroll
                    for (int n2 = 0; n2 < 2; ++n2) {
                        MMA(acc[mi][2*n2],   ah[mi], bh[n2][0], bh[n2][1]);
                        MMA(acc[mi][2*n2+1], ah[mi], bh[n2][2], bh[n2][3]);
                        MMA(acc[mi][2*n2],   al[mi], bh[n2][0], bh[n2][1]);
                        MMA(acc[mi][2*n2+1], al[mi], bh[n2][2], bh[n2][3]);
                        MMA(acc[mi][2*n2],   ah[mi], bl[n2][0], bl[n2][1]);
                        MMA(acc[mi][2*n2+1], ah[mi], bl[n2][2], bl[n2][3]);
                    }
            } else {
                #pragma unroll
                for (int mi = 0; mi < 4; ++mi)
                    #pragma unroll
                    for (int n2 = 0; n2 < 2; ++n2) {
                        MMA(acc[mi][2*n2],   ah[mi], bh[n2][0], bh[n2][1]);
                        MMA(acc[mi][2*n2+1], ah[mi], bh[n2][2], bh[n2][3]);
                    }
            }
        }
        __syncthreads();
    }

    // ---- epilogue: transpose via SMEM, coalesced float4 stores ----
    float* eps = (float*)smem;                 // [n=128][m pitch kEP]
    #pragma unroll
    for (int mi = 0; mi < 4; ++mi) {
        int m0 = warp_m * 64 + mi * 16 + (lane >> 2);
        #pragma unroll
        for (int ni = 0; ni < 4; ++ni) {
            int n0 = warp_n * 32 + ni * 8 + 2 * (lane & 3);
            eps[n0 * kEP + m0]           = acc[mi][ni][0];
            eps[(n0 + 1) * kEP + m0]     = acc[mi][ni][1];
            eps[n0 * kEP + m0 + 8]       = acc[mi][ni][2];
            eps[(n0 + 1) * kEP + m0 + 8] = acc[mi][ni][3];
        }
    }
    __syncthreads();

    int pix0 = ptile * 128;
    int m = lane * 4;
    bool ok = (pix0 + m) < HW_OUT;
    if (PATH == 0) {
        #pragma unroll 1
        for (int rr = 0; rr < 16; ++rr) {
            int r = rr * 8 + wid;
            int o = og * 128 + r;
            float4 v = *(float4*)&eps[r * kEP + m];
            float bz = bias[o];
            v.x += bz; v.y += bz; v.z += bz; v.w += bz;
            if (ok)
                *(float4*)&out[((size_t)(b * O_ + o)) * HW_OUT + pix0 + m] = v;
        }
    } else {
        float* out2 = out + (size_t)B_ * O_ * HW_OUT;
        float4 sv = make_float4(0.f, 0.f, 0.f, 0.f);
        if (ok) sv = *(float4*)&g_S[(size_t)b * HW_OUT + pix0 + m];
        #pragma unroll 1
        for (int rr = 0; rr < 16; ++rr) {
            int r = rr * 8 + wid;
            int o = og * 128 + r;
            float4 v = *(float4*)&eps[r * kEP + m];
            float sp = g_sp[o];
            v.x = (sp * sv.x + v.x) * 0.001f;
            v.y = (sp * sv.y + v.y) * 0.001f;
            v.z = (sp * sv.z + v.z) * 0.001f;
            v.w = (sp * sv.w + v.w) * 0.001f;
            if (ok)
                *(float4*)&out2[((size_t)(b * O_ + o)) * HW_OUT + pix0 + m] = v;
        }
    }
}

// ---------------------------------------------------------------------------
extern "C" void kernel_launch(void* const* d_in, const int* in_sizes, int n_in,
                              void* d_out, int out_size) {
    const float* mu_x    = (const float*)d_in[0];
    const float* sigma_x = (const float*)d_in[1];
    const float* W       = (const float*)d_in[2];
    const float* bias    = (const float*)d_in[3];
    const float* w_sigma = (const float*)d_in[4];
    float* out = (float*)d_out;

    cudaFuncSetAttribute(mma_conv_kernel<0>,
                         cudaFuncAttributeMaxDynamicSharedMemorySize, 131072);
    cudaFuncSetAttribute(mma_conv_kernel<1>,
                         cudaFuncAttributeMaxDynamicSharedMemorySize, 65536);

    {
        dim3 g(HW_IN / 64, B_, 2);                 // 144 x 16 x 2
        transpose_split_kernel<<<g, 256>>>(mu_x, sigma_x);
    }
    wprep_kernel<<<(O_ * C_ + 255) / 256, 256>>>(W, w_sigma);
    {
        int n = B_ * HW_OUT;
        boxsum_kernel<<<(n + 255) / 256, 256>>>();
    }
    {
        dim3 grid(NPT, B_, 2);                     // 67 x 16 x 2
        mma_conv_kernel<0><<<grid, 256, 131072>>>(bias, out);
        mma_conv_kernel<1><<<grid, 256, 65536>>>(bias, out);
    }
}

// round 7
// speedup vs baseline: 1.5512x; 1.5512x over previous
#include <cuda_runtime.h>
#include <cuda_bf16.h>
#include <math.h>
#include <stdint.h>

#define B_  16
#define C_  128
#define O_  256
#define H_  96
#define W_  96
#define KH  5
#define HO  92
#define WO  92
#define HW_IN  (H_*W_)        // 9216
#define HW_OUT (HO*WO)        // 8464
#define KK  25
#define NPT 67                // ceil(8464/128)
#define NSTAGE 50             // 25 taps * 2 k64-chunks

// ---------------- device scratch (no allocation allowed) ----------------
// Channel-last bf16 planes: g_Ah [path][b][pix][c], g_Al mu only [b][pix][c]
__device__ __align__(128) __nv_bfloat16 g_Ah[(size_t)2*B_*HW_IN*128];
__device__ __align__(128) __nv_bfloat16 g_Al[(size_t)B_*HW_IN*128];
// Weights: [path][og][tap][split][o_local(128)][c(128)]; path1 uses split 0 only
__device__ __align__(128) __nv_bfloat16 g_Wp[(size_t)2*2*KK*2*16384];
__device__ float g_Tp[2*B_*HW_IN];   // [path][b][pix]: path0 = sum mu^2, path1 = sum sigma
__device__ float g_S [B_*HW_OUT];
__device__ float g_sp[O_];

// ---------------- PTX helpers ----------------
__device__ __forceinline__ uint32_t smem_u32(const void* p){
    return (uint32_t)__cvta_generic_to_shared((void*)p);
}
__device__ __forceinline__ void cp16(uint32_t dst, const void* src){
    asm volatile("cp.async.cg.shared.global [%0], [%1], 16;\n" :: "r"(dst), "l"(src));
}
__device__ __forceinline__ void cp_commit(){ asm volatile("cp.async.commit_group;\n" ::: "memory"); }
template<int N> __device__ __forceinline__ void cp_wait(){
    asm volatile("cp.async.wait_group %0;\n" :: "n"(N) : "memory");
}
__device__ __forceinline__ void ldsm4(uint32_t* r, uint32_t addr){
    asm volatile("ldmatrix.sync.aligned.m8n8.x4.shared.b16 {%0,%1,%2,%3}, [%4];"
        : "=r"(r[0]), "=r"(r[1]), "=r"(r[2]), "=r"(r[3]) : "r"(addr));
}
#define MMA(acc, a, b0, b1)                                                        \
    asm volatile("mma.sync.aligned.m16n8k16.row.col.f32.bf16.bf16.f32 "            \
                 "{%0,%1,%2,%3},{%4,%5,%6,%7},{%8,%9},{%0,%1,%2,%3};"              \
                 : "+f"((acc)[0]), "+f"((acc)[1]), "+f"((acc)[2]), "+f"((acc)[3])  \
                 : "r"((a)[0]), "r"((a)[1]), "r"((a)[2]), "r"((a)[3]),             \
                   "r"(b0), "r"(b1))

// ---------------- prep kernels ----------------
__global__ void transpose_split_kernel(const float* __restrict__ mu,
                                       const float* __restrict__ sg) {
    __shared__ float ts[C_][65];
    int pt = blockIdx.x, b = blockIdx.y, path = blockIdx.z;
    const float* src = (path ? sg : mu) + (size_t)b * C_ * HW_IN + pt * 64;
    int tid = threadIdx.x;
    for (int i = tid; i < C_ * 64; i += 256) {
        int c = i >> 6, pi = i & 63;
        ts[c][pi] = src[(size_t)c * HW_IN + pi];
    }
    __syncthreads();
    size_t obase = (size_t)(path * B_ + b) * HW_IN * 128;
    int p0 = pt * 64;
    for (int i = tid; i < 64 * C_; i += 256) {
        int pi = i >> 7, c = i & 127;
        float v = ts[c][pi];
        __nv_bfloat16 hi = __float2bfloat16(v);
        size_t idx = obase + (size_t)(p0 + pi) * 128 + c;
        g_Ah[idx] = hi;
        if (path == 0)
            g_Al[(size_t)b * HW_IN * 128 + (size_t)(p0 + pi) * 128 + c] =
                __float2bfloat16(v - __bfloat162float(hi));
    }
    // fused channel sum: path0 -> sum mu^2, path1 -> sum sigma
    if (tid < 64) {
        float acc = 0.0f;
        #pragma unroll 8
        for (int c = 0; c < C_; ++c) {
            float v = ts[c][tid];
            acc += path ? v : v * v;
        }
        g_Tp[(size_t)(path * B_ + b) * HW_IN + p0 + tid] = acc;
    }
}

__global__ void wprep_kernel(const float* __restrict__ W,
                             const float* __restrict__ w_sigma) {
    int gid = blockIdx.x * blockDim.x + threadIdx.x;
    if (gid < O_) {
        float w = fmaxf(w_sigma[gid], -88.0f);
        g_sp[gid] = log1pf(expf(w));
    }
    if (gid >= O_ * C_) return;
    int o = gid >> 7, c = gid & 127;
    int og = o >> 7, ol = o & 127;
    const float* wp = W + ((size_t)o * C_ + c) * KK;
    int dst_in = ol * 128 + c;
    #pragma unroll
    for (int tap = 0; tap < KK; ++tap) {
        float w  = wp[tap];
        float w2 = w * w;
        __nv_bfloat16 h0 = __float2bfloat16(w);
        __nv_bfloat16 l0 = __float2bfloat16(w  - __bfloat162float(h0));
        size_t blk0 = (size_t)(((0 * 2 + og) * KK + tap) * 2);
        size_t blk1 = (size_t)(((1 * 2 + og) * KK + tap) * 2);
        g_Wp[(blk0 + 0) * 16384 + dst_in] = h0;
        g_Wp[(blk0 + 1) * 16384 + dst_in] = l0;
        g_Wp[(blk1 + 0) * 16384 + dst_in] = __float2bfloat16(w2);
    }
}

__global__ void boxsum_kernel() {
    int i = blockIdx.x * blockDim.x + threadIdx.x;
    if (i >= B_*HW_OUT) return;
    int b = i / HW_OUT;
    int p = i - b * HW_OUT;
    int y = p / WO;
    int x = p - y * WO;
    const float* t0 = g_Tp + (size_t)b * HW_IN;
    const float* t1 = g_Tp + (size_t)(B_ + b) * HW_IN;
    float acc = 0.0f;
    #pragma unroll
    for (int dy = 0; dy < KH; ++dy)
        #pragma unroll
        for (int dx = 0; dx < KH; ++dx) {
            int off = (y + dy) * W_ + (x + dx);
            acc += t0[off] + t1[off];
        }
    g_S[i] = acc;
}

// ---------------- main mma.sync conv (unified launch, runtime path) ----------------
// Buffer: Ah 16K | Al 16K | Bh 16K | Bl 16K = 64KB; x2 = 128KB. path1 touches Ah/Bh only.
#define BUFSZ 65536u
#define OFF_AL 16384u
#define OFF_BH 32768u
#define OFF_BL 49152u
#define SMEM_MAIN 131072

__global__ void __launch_bounds__(256, 1)
mma_conv_kernel(const float* __restrict__ bias, float* __restrict__ out) {
    extern __shared__ char smem[];
    uint32_t sb = smem_u32(smem);
    int tid = threadIdx.x;
    int lane = tid & 31, wid = tid >> 5;
    int warp_m = wid >> 2, warp_n = wid & 3;

    int ptile = blockIdx.x, b = blockIdx.y;
    int path = blockIdx.z & 1, og = blockIdx.z >> 1;

    // ---- staging setup ----
    int m_pix = tid & 127;
    int p  = ptile * 128 + m_pix;
    int pc = min(p, HW_OUT - 1);
    int py = pc / WO, px = pc - py * WO;
    const __nv_bfloat16* aplane =
        (tid < 128 ? g_Ah + (size_t)(path * B_ + b) * HW_IN * 128
                   : g_Al + (size_t)b * HW_IN * 128);
    uint32_t a_sm_off = (tid < 128 ? 0u : OFF_AL) + (uint32_t)m_pix * 128;

    int bn = tid >> 1, bhalf = tid & 1;
    const char* wbase = (const char*)g_Wp +
        (size_t)((path * 2 + og) * KK) * 2 * 32768 + (size_t)bn * 256 + bhalf * 64;
    uint32_t b_sm_base = (uint32_t)bn * 128;

    auto stage = [&](int s, int buf) {
        int tap = s >> 1, kc = s & 1;
        int ki = tap / 5, kj = tap - ki * 5;
        if (path == 0 || tid < 128) {
            const char* arow =
                (const char*)(aplane + ((size_t)((py + ki) * W_ + (px + kj))) * 128)
                + kc * 128;
            uint32_t adst = sb + buf * BUFSZ + a_sm_off;
            int msw = m_pix & 7;
            #pragma unroll
            for (int j = 0; j < 8; ++j)
                cp16(adst + (uint32_t)((j ^ msw) << 4), arow + j * 16);
        }
        const char* bsrc = wbase + (size_t)tap * 2 * 32768 + kc * 128;
        uint32_t bdst = sb + buf * BUFSZ + b_sm_base;
        int nsw = bn & 7;
        #pragma unroll
        for (int j = 0; j < 4; ++j) {
            uint32_t so = (uint32_t)(((bhalf * 4 + j) ^ nsw) << 4);
            cp16(bdst + OFF_BH + so, bsrc + j * 16);
            if (path == 0)
                cp16(bdst + OFF_BL + so, bsrc + 32768 + j * 16);
        }
        cp_commit();
    };

    uint32_t rowbaseA = (uint32_t)(warp_m * 64 + (lane & 15)) * 128;
    uint32_t rowbaseB = (uint32_t)(warp_n * 32 + ((lane >> 4) << 3) + (lane & 7)) * 128;
    int lsw = lane & 7;
    uint32_t offA[4], offB[4];
    #pragma unroll
    for (int s = 0; s < 4; ++s) {
        offA[s] = (uint32_t)(((2 * s + (lane >> 4)) ^ lsw) << 4);
        offB[s] = (uint32_t)(((2 * s + ((lane >> 3) & 1)) ^ lsw) << 4);
    }

    float acc[4][4][4];
    #pragma unroll
    for (int mi = 0; mi < 4; ++mi)
        #pragma unroll
        for (int ni = 0; ni < 4; ++ni)
            #pragma unroll
            for (int j = 0; j < 4; ++j) acc[mi][ni][j] = 0.0f;

    stage(0, 0);

    for (int s = 0; s < NSTAGE; ++s) {
        int buf = s & 1;
        if (s + 1 < NSTAGE) { stage(s + 1, buf ^ 1); cp_wait<1>(); }
        else                { cp_wait<0>(); }
        __syncthreads();

        uint32_t base = sb + buf * BUFSZ;
        uint32_t aAh = base + rowbaseA;
        uint32_t aAl = base + OFF_AL + rowbaseA;
        uint32_t aBh = base + OFF_BH + rowbaseB;
        uint32_t aBl = base + OFF_BL + rowbaseB;

        if (path == 0) {
            #pragma unroll
            for (int ks = 0; ks < 4; ++ks) {
                uint32_t ah[4][4], al[4][4], bh[2][4], bl[2][4];
                #pragma unroll
                for (int mi = 0; mi < 4; ++mi) {
                    ldsm4(ah[mi], aAh + mi * 2048 + offA[ks]);
                    ldsm4(al[mi], aAl + mi * 2048 + offA[ks]);
                }
                #pragma unroll
                for (int n2 = 0; n2 < 2; ++n2) {
                    ldsm4(bh[n2], aBh + n2 * 2048 + offB[ks]);
                    ldsm4(bl[n2], aBl + n2 * 2048 + offB[ks]);
                }
                #pragma unroll
                for (int mi = 0; mi < 4; ++mi)
                    #pragma unroll
                    for (int n2 = 0; n2 < 2; ++n2) {
                        MMA(acc[mi][2*n2],   ah[mi], bh[n2][0], bh[n2][1]);
                        MMA(acc[mi][2*n2+1], ah[mi], bh[n2][2], bh[n2][3]);
                        MMA(acc[mi][2*n2],   al[mi], bh[n2][0], bh[n2][1]);
                        MMA(acc[mi][2*n2+1], al[mi], bh[n2][2], bh[n2][3]);
                        MMA(acc[mi][2*n2],   ah[mi], bl[n2][0], bl[n2][1]);
                        MMA(acc[mi][2*n2+1], ah[mi], bl[n2][2], bl[n2][3]);
                    }
            }
        } else {
            #pragma unroll
            for (int ks = 0; ks < 4; ++ks) {
                uint32_t ah[4][4], bh[2][4];
                #pragma unroll
                for (int mi = 0; mi < 4; ++mi)
                    ldsm4(ah[mi], aAh + mi * 2048 + offA[ks]);
                #pragma unroll
                for (int n2 = 0; n2 < 2; ++n2)
                    ldsm4(bh[n2], aBh + n2 * 2048 + offB[ks]);
                #pragma unroll
                for (int mi = 0; mi < 4; ++mi)
                    #pragma unroll
                    for (int n2 = 0; n2 < 2; ++n2) {
                        MMA(acc[mi][2*n2],   ah[mi], bh[n2][0], bh[n2][1]);
                        MMA(acc[mi][2*n2+1], ah[mi], bh[n2][2], bh[n2][3]);
                    }
            }
        }
        __syncthreads();
    }

    // ---- epilogue: transpose via SMEM, coalesced float4 stores ----
    float* eps = (float*)smem;                 // [n=128][m pitch 132]
    #pragma unroll
    for (int mi = 0; mi < 4; ++mi) {
        int m0 = warp_m * 64 + mi * 16 + (lane >> 2);
        #pragma unroll
        for (int ni = 0; ni < 4; ++ni) {
            int n0 = warp_n * 32 + ni * 8 + 2 * (lane & 3);
            eps[n0 * 132 + m0]           = acc[mi][ni][0];
            eps[(n0 + 1) * 132 + m0]     = acc[mi][ni][1];
            eps[n0 * 132 + m0 + 8]       = acc[mi][ni][2];
            eps[(n0 + 1) * 132 + m0 + 8] = acc[mi][ni][3];
        }
    }
    __syncthreads();

    int pix0 = ptile * 128;
    int m = lane * 4;
    bool ok = (pix0 + m) < HW_OUT;
    if (path == 0) {
        #pragma unroll 1
        for (int rr = 0; rr < 16; ++rr) {
            int r = rr * 8 + wid;
            int o = og * 128 + r;
            float4 v = *(float4*)&eps[r * 132 + m];
            float bz = bias[o];
            v.x += bz; v.y += bz; v.z += bz; v.w += bz;
            if (ok)
                *(float4*)&out[((size_t)(b * O_ + o)) * HW_OUT + pix0 + m] = v;
        }
    } else {
        float* out2 = out + (size_t)B_ * O_ * HW_OUT;
        float4 sv = make_float4(0.f, 0.f, 0.f, 0.f);
        if (ok) sv = *(float4*)&g_S[(size_t)b * HW_OUT + pix0 + m];
        #pragma unroll 1
        for (int rr = 0; rr < 16; ++rr) {
            int r = rr * 8 + wid;
            int o = og * 128 + r;
            float4 v = *(float4*)&eps[r * 132 + m];
            float sp = g_sp[o];
            v.x = (sp * sv.x + v.x) * 0.001f;
            v.y = (sp * sv.y + v.y) * 0.001f;
            v.z = (sp * sv.z + v.z) * 0.001f;
            v.w = (sp * sv.w + v.w) * 0.001f;
            if (ok)
                *(float4*)&out2[((size_t)(b * O_ + o)) * HW_OUT + pix0 + m] = v;
        }
    }
}

// ---------------------------------------------------------------------------
extern "C" void kernel_launch(void* const* d_in, const int* in_sizes, int n_in,
                              void* d_out, int out_size) {
    const float* mu_x    = (const float*)d_in[0];
    const float* sigma_x = (const float*)d_in[1];
    const float* W       = (const float*)d_in[2];
    const float* bias    = (const float*)d_in[3];
    const float* w_sigma = (const float*)d_in[4];
    float* out = (float*)d_out;

    cudaFuncSetAttribute(mma_conv_kernel,
                         cudaFuncAttributeMaxDynamicSharedMemorySize, SMEM_MAIN);

    {
        dim3 g(HW_IN / 64, B_, 2);                 // 144 x 16 x 2
        transpose_split_kernel<<<g, 256>>>(mu_x, sigma_x);
    }
    wprep_kernel<<<(O_ * C_ + 255) / 256, 256>>>(W, w_sigma);
    {
        int n = B_ * HW_OUT;
        boxsum_kernel<<<(n + 255) / 256, 256>>>();
    }
    {
        dim3 grid(NPT, B_, 4);                     // 67 x 16 x 4 = 4288 CTAs (unified)
        mma_conv_kernel<<<grid, 256, SMEM_MAIN>>>(bias, out);
    }
}

// round 9
// speedup vs baseline: 1.9295x; 1.2439x over previous
#include <cuda_runtime.h>
#include <cuda_bf16.h>
#include <math.h>
#include <stdint.h>

#define B_  16
#define C_  128
#define O_  256
#define H_  96
#define W_  96
#define KH  5
#define HO  92
#define WO  92
#define HW_IN  (H_*W_)        // 9216
#define HW_OUT (HO*WO)        // 8464
#define KK  25
#define NPT 67                // ceil(8464/128)
#define NSTAGE 100            // 25 taps * 4 k32-chunks

// ---------------- device scratch (no allocation allowed) ----------------
__device__ __align__(128) __nv_bfloat16 g_Ah[(size_t)2*B_*HW_IN*128];
__device__ __align__(128) __nv_bfloat16 g_Al[(size_t)B_*HW_IN*128];
// Weights: [path][og][tap][split][o_local(128)][c(128)]; path1 uses split 0 only
__device__ __align__(128) __nv_bfloat16 g_Wp[(size_t)2*2*KK*2*16384];
__device__ float g_Tp[2*B_*HW_IN];
__device__ float g_S [B_*HW_OUT];
__device__ float g_sp[O_];

// ---------------- PTX helpers ----------------
__device__ __forceinline__ uint32_t smem_u32(const void* p){
    return (uint32_t)__cvta_generic_to_shared((void*)p);
}
__device__ __forceinline__ void cp16(uint32_t dst, const void* src){
    asm volatile("cp.async.cg.shared.global [%0], [%1], 16;\n" :: "r"(dst), "l"(src));
}
__device__ __forceinline__ void cp_commit(){ asm volatile("cp.async.commit_group;\n" ::: "memory"); }
template<int N> __device__ __forceinline__ void cp_wait(){
    asm volatile("cp.async.wait_group %0;\n" :: "n"(N) : "memory");
}
__device__ __forceinline__ void ldsm4(uint32_t* r, uint32_t addr){
    asm volatile("ldmatrix.sync.aligned.m8n8.x4.shared.b16 {%0,%1,%2,%3}, [%4];"
        : "=r"(r[0]), "=r"(r[1]), "=r"(r[2]), "=r"(r[3]) : "r"(addr));
}
#define MMA(acc, a, b0, b1)                                                        \
    asm volatile("mma.sync.aligned.m16n8k16.row.col.f32.bf16.bf16.f32 "            \
                 "{%0,%1,%2,%3},{%4,%5,%6,%7},{%8,%9},{%0,%1,%2,%3};"              \
                 : "+f"((acc)[0]), "+f"((acc)[1]), "+f"((acc)[2]), "+f"((acc)[3])  \
                 : "r"((a)[0]), "r"((a)[1]), "r"((a)[2]), "r"((a)[3]),             \
                   "r"(b0), "r"(b1))

// ---------------- prep kernels ----------------
__global__ void transpose_split_kernel(const float* __restrict__ mu,
                                       const float* __restrict__ sg) {
    __shared__ float ts[C_][65];
    int pt = blockIdx.x, b = blockIdx.y, path = blockIdx.z;
    const float* src = (path ? sg : mu) + (size_t)b * C_ * HW_IN + pt * 64;
    int tid = threadIdx.x;
    for (int i = tid; i < C_ * 64; i += 256) {
        int c = i >> 6, pi = i & 63;
        ts[c][pi] = src[(size_t)c * HW_IN + pi];
    }
    __syncthreads();
    size_t obase = (size_t)(path * B_ + b) * HW_IN * 128;
    int p0 = pt * 64;
    for (int i = tid; i < 64 * C_; i += 256) {
        int pi = i >> 7, c = i & 127;
        float v = ts[c][pi];
        __nv_bfloat16 hi = __float2bfloat16(v);
        size_t idx = obase + (size_t)(p0 + pi) * 128 + c;
        g_Ah[idx] = hi;
        if (path == 0)
            g_Al[(size_t)b * HW_IN * 128 + (size_t)(p0 + pi) * 128 + c] =
                __float2bfloat16(v - __bfloat162float(hi));
    }
    if (tid < 64) {
        float acc = 0.0f;
        #pragma unroll 8
        for (int c = 0; c < C_; ++c) {
            float v = ts[c][tid];
            acc += path ? v : v * v;
        }
        g_Tp[(size_t)(path * B_ + b) * HW_IN + p0 + tid] = acc;
    }
}

__global__ void wprep_kernel(const float* __restrict__ W,
                             const float* __restrict__ w_sigma) {
    int gid = blockIdx.x * blockDim.x + threadIdx.x;
    if (gid < O_) {
        float w = fmaxf(w_sigma[gid], -88.0f);
        g_sp[gid] = log1pf(expf(w));
    }
    if (gid >= O_ * C_) return;
    int o = gid >> 7, c = gid & 127;
    int og = o >> 7, ol = o & 127;
    const float* wp = W + ((size_t)o * C_ + c) * KK;
    int dst_in = ol * 128 + c;
    #pragma unroll
    for (int tap = 0; tap < KK; ++tap) {
        float w  = wp[tap];
        float w2 = w * w;
        __nv_bfloat16 h0 = __float2bfloat16(w);
        __nv_bfloat16 l0 = __float2bfloat16(w  - __bfloat162float(h0));
        size_t blk0 = (size_t)(((0 * 2 + og) * KK + tap) * 2);
        size_t blk1 = (size_t)(((1 * 2 + og) * KK + tap) * 2);
        g_Wp[(blk0 + 0) * 16384 + dst_in] = h0;
        g_Wp[(blk0 + 1) * 16384 + dst_in] = l0;
        g_Wp[(blk1 + 0) * 16384 + dst_in] = __float2bfloat16(w2);
    }
}

__global__ void boxsum_kernel() {
    int i = blockIdx.x * blockDim.x + threadIdx.x;
    if (i >= B_*HW_OUT) return;
    int b = i / HW_OUT;
    int p = i - b * HW_OUT;
    int y = p / WO;
    int x = p - y * WO;
    const float* t0 = g_Tp + (size_t)b * HW_IN;
    const float* t1 = g_Tp + (size_t)(B_ + b) * HW_IN;
    float acc = 0.0f;
    #pragma unroll
    for (int dy = 0; dy < KH; ++dy)
        #pragma unroll
        for (int dx = 0; dx < KH; ++dx) {
            int off = (y + dy) * W_ + (x + dx);
            acc += t0[off] + t1[off];
        }
    g_S[i] = acc;
}

// ---------------- main mma.sync conv: k32 stages, ring-3, 2 CTA/SM ----------------
// Buffer (32KB): Ah 8K | Al 8K | Bh 8K | Bl 8K. Ring of 3 = 96KB. path1 uses Ah/Bh.
// 64B k32 rows packed in pairs per 128B line, swizzle: (row>>1)*128 + (row&1)*64
//   + ((chunk ^ ((row>>1)&3))<<4)  -> conflict-free ldmatrix phases.
#define BUFSZ   32768u
#define OFF_AL  8192u
#define OFF_BH  16384u
#define OFF_BL  24576u
#define SMEM_MAIN 98304

__global__ void __launch_bounds__(256, 2)
mma_conv_kernel(const float* __restrict__ bias, float* __restrict__ out) {
    extern __shared__ char smem[];
    uint32_t sb = smem_u32(smem);
    int tid = threadIdx.x;
    int lane = tid & 31, wid = tid >> 5;
    int warp_m = wid >> 2, warp_n = wid & 3;

    int ptile = blockIdx.x, b = blockIdx.y;
    int path = blockIdx.z & 1, og = blockIdx.z >> 1;

    // ---- staging setup ----
    int m_pix = tid & 127;
    int p  = ptile * 128 + m_pix;
    int pc = min(p, HW_OUT - 1);
    int py = pc / WO, px = pc - py * WO;
    const __nv_bfloat16* aplane =
        (tid < 128 ? g_Ah + (size_t)(path * B_ + b) * HW_IN * 128
                   : g_Al + (size_t)b * HW_IN * 128);
    uint32_t a_sm_base = (tid < 128 ? 0u : OFF_AL)
                       + (uint32_t)((m_pix >> 1) * 128 + (m_pix & 1) * 64);
    int aq = (m_pix >> 1) & 3;

    int br = tid >> 1;                       // weight row 0..127
    const char* wblk = (const char*)g_Wp +
        (size_t)((path * 2 + og) * KK) * 2 * 32768;
    uint32_t b_sm_base = OFF_BH + (uint32_t)((br >> 1) * 128 + (br & 1) * 64);
    int bq = (br >> 1) & 3;

    auto stage = [&](int s, int buf) {
        int tap = s >> 2, kc = s & 3;
        int ki = tap / 5, kj = tap - ki * 5;
        uint32_t base = sb + buf * BUFSZ;
        if (path == 0 || tid < 128) {
            const char* arow =
                (const char*)(aplane + ((size_t)((py + ki) * W_ + (px + kj))) * 128)
                + kc * 64;
            uint32_t adst = base + a_sm_base;
            #pragma unroll
            for (int j = 0; j < 4; ++j)
                cp16(adst + (uint32_t)((j ^ aq) << 4), arow + j * 16);
        }
        const char* bsrc = wblk + (size_t)tap * 2 * 32768
                         + (size_t)br * 256 + kc * 64 + (tid & 1) * 32;
        uint32_t bdst = base + b_sm_base;
        #pragma unroll
        for (int jj = 0; jj < 2; ++jj) {
            int j = 2 * (tid & 1) + jj;
            uint32_t so = (uint32_t)((j ^ bq) << 4);
            cp16(bdst + so, bsrc + jj * 16);
            if (path == 0)
                cp16(bdst + (OFF_BL - OFF_BH) + so, bsrc + 32768 + jj * 16);
        }
        cp_commit();
    };

    // ---- ldmatrix swizzled offsets (ks=0; ks=1 toggles bit 5) ----
    int rA = warp_m * 64 + (lane & 15);
    int cA = lane >> 4;
    uint32_t offA[4];
    #pragma unroll
    for (int mi = 0; mi < 4; ++mi) {
        int row = rA + mi * 16;
        offA[mi] = (uint32_t)((row >> 1) * 128 + (row & 1) * 64
                   + ((cA ^ ((row >> 1) & 3)) << 4));
    }
    int rB = warp_n * 32 + ((lane >> 4) << 3) + (lane & 7);
    int cB = (lane >> 3) & 1;
    uint32_t offB[2];
    #pragma unroll
    for (int n2 = 0; n2 < 2; ++n2) {
        int row = rB + n2 * 16;
        offB[n2] = (uint32_t)((row >> 1) * 128 + (row & 1) * 64
                   + ((cB ^ ((row >> 1) & 3)) << 4));
    }

    float acc[4][4][4];
    #pragma unroll
    for (int mi = 0; mi < 4; ++mi)
        #pragma unroll
        for (int ni = 0; ni < 4; ++ni)
            #pragma unroll
            for (int j = 0; j < 4; ++j) acc[mi][ni][j] = 0.0f;

    stage(0, 0);
    stage(1, 1);

    for (int s = 0; s < NSTAGE; ++s) {
        int buf = s % 3;
        // 1) guarantee my stage(s) copies landed (leave s+1 in flight)
        if (s + 1 < NSTAGE) cp_wait<1>(); else cp_wait<0>();
        // 2) publish everyone's stage(s) data; also confirms buffer (s-1)%3
        //    (== (s+2)%3) has been fully consumed by all threads
        __syncthreads();
        // 3) refill the freed buffer
        if (s + 2 < NSTAGE) stage(s + 2, (s + 2) % 3);

        uint32_t base = sb + buf * BUFSZ;

        #pragma unroll
        for (int ks = 0; ks < 2; ++ks) {
            uint32_t x = ks ? 32u : 0u;
            uint32_t ah[4][4], bh[2][4];
            #pragma unroll
            for (int mi = 0; mi < 4; ++mi)
                ldsm4(ah[mi], base + (offA[mi] ^ x));
            #pragma unroll
            for (int n2 = 0; n2 < 2; ++n2)
                ldsm4(bh[n2], base + OFF_BH + (offB[n2] ^ x));

            // term 1: ah * bh  (16 independent MMAs)
            #pragma unroll
            for (int mi = 0; mi < 4; ++mi)
                #pragma unroll
                for (int n2 = 0; n2 < 2; ++n2) {
                    MMA(acc[mi][2*n2],   ah[mi], bh[n2][0], bh[n2][1]);
                    MMA(acc[mi][2*n2+1], ah[mi], bh[n2][2], bh[n2][3]);
                }

            if (path == 0) {
                uint32_t al[4][4];
                #pragma unroll
                for (int mi = 0; mi < 4; ++mi)
                    ldsm4(al[mi], base + OFF_AL + (offA[mi] ^ x));
                // term 2: al * bh
                #pragma unroll
                for (int mi = 0; mi < 4; ++mi)
                    #pragma unroll
                    for (int n2 = 0; n2 < 2; ++n2) {
                        MMA(acc[mi][2*n2],   al[mi], bh[n2][0], bh[n2][1]);
                        MMA(acc[mi][2*n2+1], al[mi], bh[n2][2], bh[n2][3]);
                    }
                uint32_t bl[2][4];
                #pragma unroll
                for (int n2 = 0; n2 < 2; ++n2)
                    ldsm4(bl[n2], base + OFF_BL + (offB[n2] ^ x));
                // term 3: ah * bl
                #pragma unroll
                for (int mi = 0; mi < 4; ++mi)
                    #pragma unroll
                    for (int n2 = 0; n2 < 2; ++n2) {
                        MMA(acc[mi][2*n2],   ah[mi], bl[n2][0], bl[n2][1]);
                        MMA(acc[mi][2*n2+1], ah[mi], bl[n2][2], bl[n2][3]);
                    }
            }
        }
    }
    __syncthreads();

    // ---- epilogue: transpose via SMEM, coalesced float4 stores ----
    float* eps = (float*)smem;                 // [n=128][m pitch 132]
    #pragma unroll
    for (int mi = 0; mi < 4; ++mi) {
        int m0 = warp_m * 64 + mi * 16 + (lane >> 2);
        #pragma unroll
        for (int ni = 0; ni < 4; ++ni) {
            int n0 = warp_n * 32 + ni * 8 + 2 * (lane & 3);
            eps[n0 * 132 + m0]           = acc[mi][ni][0];
            eps[(n0 + 1) * 132 + m0]     = acc[mi][ni][1];
            eps[n0 * 132 + m0 + 8]       = acc[mi][ni][2];
            eps[(n0 + 1) * 132 + m0 + 8] = acc[mi][ni][3];
        }
    }
    __syncthreads();

    int pix0 = ptile * 128;
    int m = lane * 4;
    bool ok = (pix0 + m) < HW_OUT;
    if (path == 0) {
        #pragma unroll 1
        for (int rr = 0; rr < 16; ++rr) {
            int r = rr * 8 + wid;
            int o = og * 128 + r;
            float4 v = *(float4*)&eps[r * 132 + m];
            float bz = bias[o];
            v.x += bz; v.y += bz; v.z += bz; v.w += bz;
            if (ok)
                *(float4*)&out[((size_t)(b * O_ + o)) * HW_OUT + pix0 + m] = v;
        }
    } else {
        float* out2 = out + (size_t)B_ * O_ * HW_OUT;
        float4 sv = make_float4(0.f, 0.f, 0.f, 0.f);
        if (ok) sv = *(float4*)&g_S[(size_t)b * HW_OUT + pix0 + m];
        #pragma unroll 1
        for (int rr = 0; rr < 16; ++rr) {
            int r = rr * 8 + wid;
            int o = og * 128 + r;
            float4 v = *(float4*)&eps[r * 132 + m];
            float sp = g_sp[o];
            v.x = (sp * sv.x + v.x) * 0.001f;
            v.y = (sp * sv.y + v.y) * 0.001f;
            v.z = (sp * sv.z + v.z) * 0.001f;
            v.w = (sp * sv.w + v.w) * 0.001f;
            if (ok)
                *(float4*)&out2[((size_t)(b * O_ + o)) * HW_OUT + pix0 + m] = v;
        }
    }
}

// ---------------------------------------------------------------------------
extern "C" void kernel_launch(void* const* d_in, const int* in_sizes, int n_in,
                              void* d_out, int out_size) {
    const float* mu_x    = (const float*)d_in[0];
    const float* sigma_x = (const float*)d_in[1];
    const float* W       = (const float*)d_in[2];
    const float* bias    = (const float*)d_in[3];
    const float* w_sigma = (const float*)d_in[4];
    float* out = (float*)d_out;

    cudaFuncSetAttribute(mma_conv_kernel,
                         cudaFuncAttributeMaxDynamicSharedMemorySize, SMEM_MAIN);

    {
        dim3 g(HW_IN / 64, B_, 2);                 // 144 x 16 x 2
        transpose_split_kernel<<<g, 256>>>(mu_x, sigma_x);
    }
    wprep_kernel<<<(O_ * C_ + 255) / 256, 256>>>(W, w_sigma);
    {
        int n = B_ * HW_OUT;
        boxsum_kernel<<<(n + 255) / 256, 256>>>();
    }
    {
        dim3 grid(NPT, B_, 4);                     // 67 x 16 x 4 = 4288 CTAs
        mma_conv_kernel<<<grid, 256, SMEM_MAIN>>>(bias, out);
    }
}